// round 13
// baseline (speedup 1.0000x reference)
#include <cuda_runtime.h>
#include <cuda_fp16.h>
#include <stdint.h>

#define DI __device__ __forceinline__

static constexpr int B_SZ = 8192, NNB = 32, DIN = 512, DHID = 512, DOUT = 512;
static constexpr int M_ROWS1 = B_SZ * NNB;     // 262144

// ---------------- device scratch ----------------
__device__ __half g_Wt1 [DHID * DIN];            // [n][k] = mlp_w[k][n]   (K-major)
__device__ __half g_Wcat[DOUT * (DIN + DHID)];   // [n][k] = k<512 ? self_w[k][n] : neigh_w[k-512][n]
__device__ __half g_pooled[B_SZ * DHID];         // fp16 max-pooled hidden

// ---------------- PTX helpers (sm_103 baseline; no tcgen05) ----------------
DI uint32_t su32(const void* p) {
    uint32_t a;
    asm("{ .reg .u64 t; cvta.to.shared.u64 t, %1; cvt.u32.u64 %0, t; }" : "=r"(a) : "l"(p));
    return a;
}
DI void cp16(uint32_t s, const void* g) {
    asm volatile("cp.async.cg.shared.global [%0], [%1], 16;" :: "r"(s), "l"(g));
}
DI void cp_commit() { asm volatile("cp.async.commit_group;"); }
template<int N> DI void cp_wait() { asm volatile("cp.async.wait_group %0;" :: "n"(N)); }

DI void ldm4(uint32_t* r, uint32_t a) {
    asm volatile("ldmatrix.sync.aligned.m8n8.x4.shared.b16 {%0,%1,%2,%3}, [%4];"
                 : "=r"(r[0]), "=r"(r[1]), "=r"(r[2]), "=r"(r[3]) : "r"(a));
}
DI void mma16816(float* c, const uint32_t* a, const uint32_t* b) {
    asm volatile(
        "mma.sync.aligned.m16n8k16.row.col.f32.f16.f16.f32 "
        "{%0,%1,%2,%3}, {%4,%5,%6,%7}, {%8,%9}, {%0,%1,%2,%3};"
        : "+f"(c[0]), "+f"(c[1]), "+f"(c[2]), "+f"(c[3])
        : "r"(a[0]), "r"(a[1]), "r"(a[2]), "r"(a[3]), "r"(b[0]), "r"(b[1]));
}
DI uint32_t h2u(__half2 h) { return *reinterpret_cast<uint32_t*>(&h); }

// ---------------- fused prepass (R11-proven, verbatim) ----------------
__global__ void prep_k(const float* __restrict__ mlp_w,
                       const float* __restrict__ self_w,
                       const float* __restrict__ neigh_w) {
    const int job  = blockIdx.x >> 8;
    const int tile = blockIdx.x & 255;
    const float* __restrict__ src = (job == 0) ? mlp_w : (job == 1) ? self_w : neigh_w;
    __half* __restrict__ dst = (job == 0) ? g_Wt1 : g_Wcat;
    const int dstride = (job == 0) ? DIN : (DIN + DHID);
    const int koff    = (job == 2) ? DIN : 0;

    __shared__ float t[32][33];
    const int tx = threadIdx.x, ty = threadIdx.y;
    const int n0 = (tile & 15) * 32, k0 = (tile >> 4) * 32;
    #pragma unroll
    for (int j = 0; j < 4; ++j)
        t[ty + j * 8][tx] = src[(size_t)(k0 + ty + j * 8) * 512 + n0 + tx];
    __syncthreads();
    #pragma unroll
    for (int j = 0; j < 4; ++j) {
        int n = n0 + ty + j * 8, k = k0 + tx;
        dst[(size_t)n * dstride + koff + k] = __float2half(t[tx][ty + j * 8]);
    }
}

// ==================== STAGE 1: R11 config + 3-buffer ring, ONE barrier per k-tile ====================
// C[64,512] = fp16(neigh[m0..+63,:]) @ Wt1; bias+relu+max over the two 32-row
// neighbor groups -> g_pooled.  grid = 4096, 112 KB smem -> 2 CTAs/SM.
// Ring: iter it issues buf (it+1)%3 BEFORE cp_wait (R4 prefetch lead preserved);
// trailing barrier removed — overwrite target (it+1)%3 == (it-2)%3 is protected
// transitively by BARRIER(it-1) <= BARRIER(it).
__global__ void __launch_bounds__(256, 2) gemm1_k(const float* __restrict__ Af,
                                                  const float* __restrict__ bias) {
    constexpr int KTOT = 512, NIT = 32, AROW = KTOT * 2;    // 4 nb x 8 kt
    constexpr uint32_t ABYTES = 64 * AROW;                  // 64 KB
    constexpr uint32_t BB = 16384;                          // 3 buffers

    extern __shared__ char sm[];
    const uint32_t sb = su32(sm);
    const int tid = threadIdx.x;
    const int w = tid >> 5, lane = tid & 31;
    const int wm = w >> 2, wn = w & 3;            // 2 x 4 warps, warp tile 32x32
    const int lr = lane & 7, lg = lane >> 3;
    const int m0 = blockIdx.x * 64;

    auto As = [&](int m, int k8) -> uint32_t {
        return sb + (uint32_t)(m * AROW + ((k8 ^ (m & 7)) << 4));
    };
    auto Bs = [&](int s, int n, int k8) -> uint32_t {
        return sb + ABYTES + (uint32_t)s * BB + (uint32_t)(n * 128 + ((k8 ^ (n & 7)) << 4));
    };
    auto issueB = [&](int it) {                   // it = nb*8+kt, buffer it%3
        int s = it % 3, nb = it >> 3, kt = it & 7;
        #pragma unroll
        for (int i = 0; i < 4; ++i) {             // 128 n x 8 chunks
            int ch = tid + i * 256;
            int n = ch >> 3, k8 = ch & 7;
            cp16(Bs(s, n, k8), g_Wt1 + (size_t)(nb * 128 + n) * KTOT + kt * 64 + k8 * 8);
        }
        cp_commit();
    };

    issueB(0);       // overlap first weight fetch with the A-load below

    // ---- A tile: 64 rows x 512 fp32 -> fp16 smem (R11 verbatim) ----
    #pragma unroll
    for (int c = 0; c < 16; ++c) {                // 64 rows x 64 chunks
        int ch = tid + c * 256;
        int m = ch >> 6, k8 = ch & 63;
        const float* gp = Af + (size_t)(m0 + m) * 512 + k8 * 8;
        float4 f0 = *reinterpret_cast<const float4*>(gp);
        float4 f1 = *reinterpret_cast<const float4*>(gp + 4);
        uint4 u;
        u.x = h2u(__floats2half2_rn(f0.x, f0.y));
        u.y = h2u(__floats2half2_rn(f0.z, f0.w));
        u.z = h2u(__floats2half2_rn(f1.x, f1.y));
        u.w = h2u(__floats2half2_rn(f1.z, f1.w));
        *reinterpret_cast<uint4*>((char*)sm + (As(m, k8) - sb)) = u;
    }
    __syncthreads();                              // A visible to all warps

    float acc[2][4][4];
    for (int it = 0; it < NIT; ++it) {
        const int nb = it >> 3, kt = it & 7, s = it % 3;
        if (kt == 0) {
            #pragma unroll
            for (int mi = 0; mi < 2; ++mi)
                #pragma unroll
                for (int ni = 0; ni < 4; ++ni)
                    #pragma unroll
                    for (int q = 0; q < 4; ++q) acc[mi][ni][q] = 0.f;
        }

        if (it + 1 < NIT) { issueB(it + 1); cp_wait<1>(); }   // issue BEFORE wait
        else              { cp_wait<0>(); }
        __syncthreads();                          // the ONLY barrier per k-tile

        #pragma unroll
        for (int ks = 0; ks < 4; ++ks) {
            const int k8g = kt * 8 + ks * 2;
            uint32_t afr[2][4];
            #pragma unroll
            for (int mi = 0; mi < 2; ++mi) {
                int m = wm * 32 + mi * 16 + (lg & 1) * 8 + lr;
                ldm4(afr[mi], As(m, k8g + (lg >> 1)));
            }
            uint32_t bfr[2][4];
            #pragma unroll
            for (int nj = 0; nj < 2; ++nj) {
                int n = wn * 32 + nj * 16 + (lg >> 1) * 8 + lr;
                ldm4(bfr[nj], Bs(s, n, ks * 2 + (lg & 1)));
            }
            #pragma unroll
            for (int mi = 0; mi < 2; ++mi)
                #pragma unroll
                for (int ni = 0; ni < 4; ++ni)
                    mma16816(acc[mi][ni], afr[mi], &bfr[ni >> 1][(ni & 1) * 2]);
        }

        if (kt == 7) {
            // ---- epilogue (register-only): warp wm's rows = neighbors of
            //      batch blockIdx*2+wm ----
            const int n0w = nb * 128 + wn * 32;
            float v0[4], v1[4];
            #pragma unroll
            for (int ni = 0; ni < 4; ++ni) {
                v0[ni] = fmaxf(fmaxf(acc[0][ni][0], acc[0][ni][2]),
                               fmaxf(acc[1][ni][0], acc[1][ni][2]));
                v1[ni] = fmaxf(fmaxf(acc[0][ni][1], acc[0][ni][3]),
                               fmaxf(acc[1][ni][1], acc[1][ni][3]));
            }
            #pragma unroll
            for (int off = 4; off < 32; off <<= 1)
                #pragma unroll
                for (int ni = 0; ni < 4; ++ni) {
                    v0[ni] = fmaxf(v0[ni], __shfl_xor_sync(0xffffffffu, v0[ni], off));
                    v1[ni] = fmaxf(v1[ni], __shfl_xor_sync(0xffffffffu, v1[ni], off));
                }
            if (lane < 4) {
                size_t batch = (size_t)blockIdx.x * 2 + wm;
                #pragma unroll
                for (int ni = 0; ni < 4; ++ni) {
                    int col = n0w + ni * 8 + lane * 2;
                    float a0 = fmaxf(v0[ni] + __ldg(bias + col),     0.f);
                    float a1 = fmaxf(v1[ni] + __ldg(bias + col + 1), 0.f);
                    *reinterpret_cast<__half2*>(g_pooled + batch * DHID + col) =
                        __floats2half2_rn(a0, a1);
                }
            }
        }
    }
}

// ==================== STAGE 2 (R11-proven, verbatim) ====================
__global__ void __launch_bounds__(256, 1) gemm2_k(const float* __restrict__ selfv,
                                                  float* __restrict__ out) {
    constexpr int KTOT = 1024, NKT = 16, AROW = KTOT * 2;
    constexpr uint32_t ABYTES = 64 * AROW;                  // 128 KB
    constexpr uint32_t BS0 = ABYTES, BS1 = ABYTES + 16384;

    extern __shared__ char sm[];
    const uint32_t sb = su32(sm);
    const int tid = threadIdx.x;
    const int w = tid >> 5, lane = tid & 31;
    const int wm = w >> 2, wn = w & 3;
    const int lr = lane & 7, lg = lane >> 3;
    const int m0 = blockIdx.x * 64;

    auto As = [&](int m, int k8) -> uint32_t {
        return sb + (uint32_t)(m * AROW + ((k8 ^ (m & 7)) << 4));
    };
    auto Bs = [&](int buf, int n, int k8) -> uint32_t {
        return sb + (buf ? BS1 : BS0) + (uint32_t)(n * 128 + ((k8 ^ (n & 7)) << 4));
    };
    auto issueB = [&](int nb, int kt) {
        int buf = kt & 1;
        #pragma unroll
        for (int i = 0; i < 4; ++i) {
            int ch = tid + i * 256;
            int n = ch >> 3, k8 = ch & 7;
            cp16(Bs(buf, n, k8), g_Wcat + (size_t)(nb * 128 + n) * KTOT + kt * 64 + k8 * 8);
        }
        cp_commit();
    };

    issueB(0, 0);

    // ---- A tile, k[0:512): fp32 self_vecs converted inline ----
    #pragma unroll
    for (int c = 0; c < 16; ++c) {                // 64 rows x 64 chunks
        int ch = tid + c * 256;
        int m = ch >> 6, k8 = ch & 63;
        const float* gp = selfv + (size_t)(m0 + m) * 512 + k8 * 8;
        float4 f0 = *reinterpret_cast<const float4*>(gp);
        float4 f1 = *reinterpret_cast<const float4*>(gp + 4);
        uint4 u;
        u.x = h2u(__floats2half2_rn(f0.x, f0.y));
        u.y = h2u(__floats2half2_rn(f0.z, f0.w));
        u.z = h2u(__floats2half2_rn(f1.x, f1.y));
        u.w = h2u(__floats2half2_rn(f1.z, f1.w));
        *reinterpret_cast<uint4*>((char*)sm + (As(m, k8) - sb)) = u;
    }
    // ---- A tile, k[512:1024): fp16 pooled copy ----
    #pragma unroll
    for (int c = 0; c < 16; ++c) {                // 64 rows x 64 chunks
        int ch = tid + c * 256;
        int m = ch >> 6, k8 = ch & 63;
        *reinterpret_cast<uint4*>((char*)sm + (As(m, 64 + k8) - sb)) =
            *reinterpret_cast<const uint4*>(g_pooled + (size_t)(m0 + m) * DHID + k8 * 8);
    }
    __syncthreads();

    for (int nb = 0; nb < 4; ++nb) {
        float acc[2][4][4];
        #pragma unroll
        for (int mi = 0; mi < 2; ++mi)
            #pragma unroll
            for (int ni = 0; ni < 4; ++ni)
                #pragma unroll
                for (int q = 0; q < 4; ++q) acc[mi][ni][q] = 0.f;

        if (nb > 0) issueB(nb, 0);
        for (int kt = 0; kt < NKT; ++kt) {
            if (kt + 1 < NKT) { issueB(nb, kt + 1); cp_wait<1>(); }
            else             { cp_wait<0>(); }
            __syncthreads();

            const int buf = kt & 1;
            #pragma unroll
            for (int ks = 0; ks < 4; ++ks) {
                const int k8g = kt * 8 + ks * 2;
                uint32_t afr[2][4];
                #pragma unroll
                for (int mi = 0; mi < 2; ++mi) {
                    int m = wm * 32 + mi * 16 + (lg & 1) * 8 + lr;
                    ldm4(afr[mi], As(m, k8g + (lg >> 1)));
                }
                uint32_t bfr[2][4];
                #pragma unroll
                for (int nj = 0; nj < 2; ++nj) {
                    int n = wn * 32 + nj * 16 + (lg >> 1) * 8 + lr;
                    ldm4(bfr[nj], Bs(buf, n, ks * 2 + (lg & 1)));
                }
                #pragma unroll
                for (int mi = 0; mi < 2; ++mi)
                    #pragma unroll
                    for (int ni = 0; ni < 4; ++ni)
                        mma16816(acc[mi][ni], afr[mi], &bfr[ni >> 1][(ni & 1) * 2]);
            }
            __syncthreads();
        }

        const int n0w = nb * 128 + wn * 32;
        #pragma unroll
        for (int mi = 0; mi < 2; ++mi)
            #pragma unroll
            for (int h = 0; h < 2; ++h) {
                int m = m0 + wm * 32 + mi * 16 + (lane >> 2) + h * 8;
                #pragma unroll
                for (int ni = 0; ni < 4; ++ni) {
                    int col = n0w + ni * 8 + (lane & 3) * 2;
                    float2 v = make_float2(fmaxf(acc[mi][ni][h * 2],     0.f),
                                           fmaxf(acc[mi][ni][h * 2 + 1], 0.f));
                    *reinterpret_cast<float2*>(out + (size_t)m * DOUT + col) = v;
                }
            }
        __syncthreads();
    }
}

// ---------------- launch: 3 kernels total ----------------
extern "C" void kernel_launch(void* const* d_in, const int* in_sizes, int n_in,
                              void* d_out, int out_size) {
    const float* self_vecs = (const float*)d_in[0];
    const float* neigh     = (const float*)d_in[1];
    const float* mlp_w     = (const float*)d_in[2];
    const float* mlp_b     = (const float*)d_in[3];
    const float* neigh_w   = (const float*)d_in[4];
    const float* self_w    = (const float*)d_in[5];
    float* out = (float*)d_out;

    constexpr uint32_t SMEM1 = 64 * 1024 + 3 * 16384;    // 112 KB -> 2 CTAs/SM (224<=228)
    constexpr uint32_t SMEM2 = 128 * 1024 + 2 * 16384;   // 160 KB -> 1 CTA/SM
    cudaFuncSetAttribute(gemm1_k, cudaFuncAttributeMaxDynamicSharedMemorySize, SMEM1);
    cudaFuncSetAttribute(gemm2_k, cudaFuncAttributeMaxDynamicSharedMemorySize, SMEM2);

    prep_k<<<768, dim3(32, 8)>>>(mlp_w, self_w, neigh_w);
    gemm1_k<<<M_ROWS1 / 64, 256, SMEM1>>>(neigh, mlp_b);
    gemm2_k<<<B_SZ / 64, 256, SMEM2>>>(self_vecs, out);
}

// round 14
// speedup vs baseline: 1.1084x; 1.1084x over previous
#include <cuda_runtime.h>
#include <cuda_fp16.h>
#include <stdint.h>

#define DI __device__ __forceinline__

static constexpr int B_SZ = 8192, NNB = 32, DIN = 512, DHID = 512, DOUT = 512;
static constexpr int M_ROWS1 = B_SZ * NNB;     // 262144

// ---------------- device scratch ----------------
__device__ __half g_Wt1 [DHID * DIN];            // [n][k] = mlp_w[k][n]   (K-major)
__device__ __half g_Wcat[DOUT * (DIN + DHID)];   // [n][k] = k<512 ? self_w[k][n] : neigh_w[k-512][n]
__device__ __half g_pooled[B_SZ * DHID];         // fp16 max-pooled hidden

// ---------------- PTX helpers (sm_103 baseline; no tcgen05) ----------------
DI uint32_t su32(const void* p) {
    uint32_t a;
    asm("{ .reg .u64 t; cvta.to.shared.u64 t, %1; cvt.u32.u64 %0, t; }" : "=r"(a) : "l"(p));
    return a;
}
DI void cp16(uint32_t s, const void* g) {
    asm volatile("cp.async.cg.shared.global [%0], [%1], 16;" :: "r"(s), "l"(g));
}
DI void cp_commit() { asm volatile("cp.async.commit_group;"); }
template<int N> DI void cp_wait() { asm volatile("cp.async.wait_group %0;" :: "n"(N)); }

DI void ldm4(uint32_t* r, uint32_t a) {
    asm volatile("ldmatrix.sync.aligned.m8n8.x4.shared.b16 {%0,%1,%2,%3}, [%4];"
                 : "=r"(r[0]), "=r"(r[1]), "=r"(r[2]), "=r"(r[3]) : "r"(a));
}
DI void mma16816(float* c, const uint32_t* a, const uint32_t* b) {
    asm volatile(
        "mma.sync.aligned.m16n8k16.row.col.f32.f16.f16.f32 "
        "{%0,%1,%2,%3}, {%4,%5,%6,%7}, {%8,%9}, {%0,%1,%2,%3};"
        : "+f"(c[0]), "+f"(c[1]), "+f"(c[2]), "+f"(c[3])
        : "r"(a[0]), "r"(a[1]), "r"(a[2]), "r"(a[3]), "r"(b[0]), "r"(b[1]));
}
DI uint32_t h2u(__half2 h) { return *reinterpret_cast<uint32_t*>(&h); }

// ---------------- fused prepass: 3 transposes in ONE launch ----------------
// job 0: mlp_w  [512x512] -> g_Wt1  (dstride 512,  koff 0)
// job 1: self_w [512x512] -> g_Wcat (dstride 1024, koff 0)
// job 2: neigh_w[512x512] -> g_Wcat (dstride 1024, koff 512)
// 768 blocks of (32,8). dst __device__ symbol selected in device code (R8 rule).
__global__ void prep_k(const float* __restrict__ mlp_w,
                       const float* __restrict__ self_w,
                       const float* __restrict__ neigh_w) {
    const int job  = blockIdx.x >> 8;
    const int tile = blockIdx.x & 255;
    const float* __restrict__ src = (job == 0) ? mlp_w : (job == 1) ? self_w : neigh_w;
    __half* __restrict__ dst = (job == 0) ? g_Wt1 : g_Wcat;
    const int dstride = (job == 0) ? DIN : (DIN + DHID);
    const int koff    = (job == 2) ? DIN : 0;

    __shared__ float t[32][33];
    const int tx = threadIdx.x, ty = threadIdx.y;
    const int n0 = (tile & 15) * 32, k0 = (tile >> 4) * 32;
    #pragma unroll
    for (int j = 0; j < 4; ++j)
        t[ty + j * 8][tx] = src[(size_t)(k0 + ty + j * 8) * 512 + n0 + tx];
    __syncthreads();
    #pragma unroll
    for (int j = 0; j < 4; ++j) {
        int n = n0 + ty + j * 8, k = k0 + tx;
        dst[(size_t)n * dstride + koff + k] = __float2half(t[tx][ty + j * 8]);
    }
}

// ==================== STAGE 1 (R4/R8-proven 430.5us config, verbatim) ====================
// C[64,512] = fp16(neigh[m0..+63,:]) @ Wt1; bias+relu+max over the two 32-row
// neighbor groups -> g_pooled.  grid = 4096, 96 KB smem -> 2 CTAs/SM.
__global__ void __launch_bounds__(256, 2) gemm1_k(const float* __restrict__ Af,
                                                  const float* __restrict__ bias) {
    constexpr int KTOT = 512, NKT = 8, AROW = KTOT * 2;
    constexpr uint32_t ABYTES = 64 * AROW;                  // 64 KB
    constexpr uint32_t BS0 = ABYTES, BS1 = ABYTES + 16384;

    extern __shared__ char sm[];
    const uint32_t sb = su32(sm);
    const int tid = threadIdx.x;
    const int w = tid >> 5, lane = tid & 31;
    const int wm = w >> 2, wn = w & 3;            // 2 x 4 warps, warp tile 32x32
    const int lr = lane & 7, lg = lane >> 3;
    const int m0 = blockIdx.x * 64;

    auto As = [&](int m, int k8) -> uint32_t {
        return sb + (uint32_t)(m * AROW + ((k8 ^ (m & 7)) << 4));
    };
    auto Bs = [&](int buf, int n, int k8) -> uint32_t {
        return sb + (buf ? BS1 : BS0) + (uint32_t)(n * 128 + ((k8 ^ (n & 7)) << 4));
    };
    auto issueB = [&](int nb, int kt) {
        int buf = kt & 1;
        #pragma unroll
        for (int i = 0; i < 4; ++i) {             // 128 n x 8 chunks
            int ch = tid + i * 256;
            int n = ch >> 3, k8 = ch & 7;
            cp16(Bs(buf, n, k8), g_Wt1 + (size_t)(nb * 128 + n) * KTOT + kt * 64 + k8 * 8);
        }
        cp_commit();
    };

    issueB(0, 0);    // overlap first weight fetch with the A-load below

    // ---- A tile: 64 rows x 512 fp32 -> fp16 smem ----
    #pragma unroll
    for (int c = 0; c < 16; ++c) {                // 64 rows x 64 chunks
        int ch = tid + c * 256;
        int m = ch >> 6, k8 = ch & 63;
        const float* gp = Af + (size_t)(m0 + m) * 512 + k8 * 8;
        float4 f0 = *reinterpret_cast<const float4*>(gp);
        float4 f1 = *reinterpret_cast<const float4*>(gp + 4);
        uint4 u;
        u.x = h2u(__floats2half2_rn(f0.x, f0.y));
        u.y = h2u(__floats2half2_rn(f0.z, f0.w));
        u.z = h2u(__floats2half2_rn(f1.x, f1.y));
        u.w = h2u(__floats2half2_rn(f1.z, f1.w));
        *reinterpret_cast<uint4*>((char*)sm + (As(m, k8) - sb)) = u;
    }
    __syncthreads();

    for (int nb = 0; nb < 4; ++nb) {
        float acc[2][4][4];
        #pragma unroll
        for (int mi = 0; mi < 2; ++mi)
            #pragma unroll
            for (int ni = 0; ni < 4; ++ni)
                #pragma unroll
                for (int q = 0; q < 4; ++q) acc[mi][ni][q] = 0.f;

        if (nb > 0) issueB(nb, 0);
        for (int kt = 0; kt < NKT; ++kt) {
            if (kt + 1 < NKT) { issueB(nb, kt + 1); cp_wait<1>(); }
            else             { cp_wait<0>(); }
            __syncthreads();

            const int buf = kt & 1;
            #pragma unroll
            for (int ks = 0; ks < 4; ++ks) {
                const int k8g = kt * 8 + ks * 2;
                uint32_t afr[2][4];
                #pragma unroll
                for (int mi = 0; mi < 2; ++mi) {
                    int m = wm * 32 + mi * 16 + (lg & 1) * 8 + lr;
                    ldm4(afr[mi], As(m, k8g + (lg >> 1)));
                }
                uint32_t bfr[2][4];
                #pragma unroll
                for (int nj = 0; nj < 2; ++nj) {
                    int n = wn * 32 + nj * 16 + (lg >> 1) * 8 + lr;
                    ldm4(bfr[nj], Bs(buf, n, ks * 2 + (lg & 1)));
                }
                #pragma unroll
                for (int mi = 0; mi < 2; ++mi)
                    #pragma unroll
                    for (int ni = 0; ni < 4; ++ni)
                        mma16816(acc[mi][ni], afr[mi], &bfr[ni >> 1][(ni & 1) * 2]);
            }
            __syncthreads();
        }

        // ---- epilogue: warp wm's 32 rows = neighbors of batch blockIdx*2+wm ----
        const int n0w = nb * 128 + wn * 32;
        float v0[4], v1[4];
        #pragma unroll
        for (int ni = 0; ni < 4; ++ni) {
            v0[ni] = fmaxf(fmaxf(acc[0][ni][0], acc[0][ni][2]),
                           fmaxf(acc[1][ni][0], acc[1][ni][2]));
            v1[ni] = fmaxf(fmaxf(acc[0][ni][1], acc[0][ni][3]),
                           fmaxf(acc[1][ni][1], acc[1][ni][3]));
        }
        #pragma unroll
        for (int off = 4; off < 32; off <<= 1)
            #pragma unroll
            for (int ni = 0; ni < 4; ++ni) {
                v0[ni] = fmaxf(v0[ni], __shfl_xor_sync(0xffffffffu, v0[ni], off));
                v1[ni] = fmaxf(v1[ni], __shfl_xor_sync(0xffffffffu, v1[ni], off));
            }
        if (lane < 4) {
            size_t batch = (size_t)blockIdx.x * 2 + wm;
            #pragma unroll
            for (int ni = 0; ni < 4; ++ni) {
                int col = n0w + ni * 8 + lane * 2;
                float a0 = fmaxf(v0[ni] + __ldg(bias + col),     0.f);
                float a1 = fmaxf(v1[ni] + __ldg(bias + col + 1), 0.f);
                *reinterpret_cast<__half2*>(g_pooled + batch * DHID + col) =
                    __floats2half2_rn(a0, a1);
            }
        }
        __syncthreads();   // before next nb overwrites B buffers
    }
}

// ==================== STAGE 2 (R8-proven mainloop; A-loader converts self inline) ====================
// C[64,512] = [fp16(self_vecs)|pooled][m0..+63,:] @ Wcat; relu -> out. grid=128, 160 KB.
__global__ void __launch_bounds__(256, 1) gemm2_k(const float* __restrict__ selfv,
                                                  float* __restrict__ out) {
    constexpr int KTOT = 1024, NKT = 16, AROW = KTOT * 2;
    constexpr uint32_t ABYTES = 64 * AROW;                  // 128 KB
    constexpr uint32_t BS0 = ABYTES, BS1 = ABYTES + 16384;

    extern __shared__ char sm[];
    const uint32_t sb = su32(sm);
    const int tid = threadIdx.x;
    const int w = tid >> 5, lane = tid & 31;
    const int wm = w >> 2, wn = w & 3;
    const int lr = lane & 7, lg = lane >> 3;
    const int m0 = blockIdx.x * 64;

    auto As = [&](int m, int k8) -> uint32_t {
        return sb + (uint32_t)(m * AROW + ((k8 ^ (m & 7)) << 4));
    };
    auto Bs = [&](int buf, int n, int k8) -> uint32_t {
        return sb + (buf ? BS1 : BS0) + (uint32_t)(n * 128 + ((k8 ^ (n & 7)) << 4));
    };
    auto issueB = [&](int nb, int kt) {
        int buf = kt & 1;
        #pragma unroll
        for (int i = 0; i < 4; ++i) {
            int ch = tid + i * 256;
            int n = ch >> 3, k8 = ch & 7;
            cp16(Bs(buf, n, k8), g_Wcat + (size_t)(nb * 128 + n) * KTOT + kt * 64 + k8 * 8);
        }
        cp_commit();
    };

    issueB(0, 0);

    // ---- A tile, k[0:512): fp32 self_vecs converted inline (same rounding as conv_k) ----
    #pragma unroll
    for (int c = 0; c < 16; ++c) {                // 64 rows x 64 chunks
        int ch = tid + c * 256;
        int m = ch >> 6, k8 = ch & 63;
        const float* gp = selfv + (size_t)(m0 + m) * 512 + k8 * 8;
        float4 f0 = *reinterpret_cast<const float4*>(gp);
        float4 f1 = *reinterpret_cast<const float4*>(gp + 4);
        uint4 u;
        u.x = h2u(__floats2half2_rn(f0.x, f0.y));
        u.y = h2u(__floats2half2_rn(f0.z, f0.w));
        u.z = h2u(__floats2half2_rn(f1.x, f1.y));
        u.w = h2u(__floats2half2_rn(f1.z, f1.w));
        *reinterpret_cast<uint4*>((char*)sm + (As(m, k8) - sb)) = u;
    }
    // ---- A tile, k[512:1024): fp16 pooled copy. Chunk index 64+k8: the XOR swizzle
    //      only touches the low 3 bits, so (64+k8)^(m&7) == 64 + (k8^(m&7)) — layout
    //      is byte-identical to the previous g_selfh/g_pooled staging. ----
    #pragma unroll
    for (int c = 0; c < 16; ++c) {                // 64 rows x 64 chunks
        int ch = tid + c * 256;
        int m = ch >> 6, k8 = ch & 63;
        *reinterpret_cast<uint4*>((char*)sm + (As(m, 64 + k8) - sb)) =
            *reinterpret_cast<const uint4*>(g_pooled + (size_t)(m0 + m) * DHID + k8 * 8);
    }
    __syncthreads();

    for (int nb = 0; nb < 4; ++nb) {
        float acc[2][4][4];
        #pragma unroll
        for (int mi = 0; mi < 2; ++mi)
            #pragma unroll
            for (int ni = 0; ni < 4; ++ni)
                #pragma unroll
                for (int q = 0; q < 4; ++q) acc[mi][ni][q] = 0.f;

        if (nb > 0) issueB(nb, 0);
        for (int kt = 0; kt < NKT; ++kt) {
            if (kt + 1 < NKT) { issueB(nb, kt + 1); cp_wait<1>(); }
            else             { cp_wait<0>(); }
            __syncthreads();

            const int buf = kt & 1;
            #pragma unroll
            for (int ks = 0; ks < 4; ++ks) {
                const int k8g = kt * 8 + ks * 2;
                uint32_t afr[2][4];
                #pragma unroll
                for (int mi = 0; mi < 2; ++mi) {
                    int m = wm * 32 + mi * 16 + (lg & 1) * 8 + lr;
                    ldm4(afr[mi], As(m, k8g + (lg >> 1)));
                }
                uint32_t bfr[2][4];
                #pragma unroll
                for (int nj = 0; nj < 2; ++nj) {
                    int n = wn * 32 + nj * 16 + (lg >> 1) * 8 + lr;
                    ldm4(bfr[nj], Bs(buf, n, ks * 2 + (lg & 1)));
                }
                #pragma unroll
                for (int mi = 0; mi < 2; ++mi)
                    #pragma unroll
                    for (int ni = 0; ni < 4; ++ni)
                        mma16816(acc[mi][ni], afr[mi], &bfr[ni >> 1][(ni & 1) * 2]);
            }
            __syncthreads();
        }

        const int n0w = nb * 128 + wn * 32;
        #pragma unroll
        for (int mi = 0; mi < 2; ++mi)
            #pragma unroll
            for (int h = 0; h < 2; ++h) {
                int m = m0 + wm * 32 + mi * 16 + (lane >> 2) + h * 8;
                #pragma unroll
                for (int ni = 0; ni < 4; ++ni) {
                    int col = n0w + ni * 8 + (lane & 3) * 2;
                    float2 v = make_float2(fmaxf(acc[mi][ni][h * 2],     0.f),
                                           fmaxf(acc[mi][ni][h * 2 + 1], 0.f));
                    *reinterpret_cast<float2*>(out + (size_t)m * DOUT + col) = v;
                }
            }
        __syncthreads();
    }
}

// ---------------- launch: 3 kernels total ----------------
extern "C" void kernel_launch(void* const* d_in, const int* in_sizes, int n_in,
                              void* d_out, int out_size) {
    const float* self_vecs = (const float*)d_in[0];
    const float* neigh     = (const float*)d_in[1];
    const float* mlp_w     = (const float*)d_in[2];
    const float* mlp_b     = (const float*)d_in[3];
    const float* neigh_w   = (const float*)d_in[4];
    const float* self_w    = (const float*)d_in[5];
    float* out = (float*)d_out;

    constexpr uint32_t SMEM1 = 64 * 1024 + 2 * 16384;    //  96 KB -> 2 CTAs/SM
    constexpr uint32_t SMEM2 = 128 * 1024 + 2 * 16384;   // 160 KB -> 1 CTA/SM
    cudaFuncSetAttribute(gemm1_k, cudaFuncAttributeMaxDynamicSharedMemorySize, SMEM1);
    cudaFuncSetAttribute(gemm2_k, cudaFuncAttributeMaxDynamicSharedMemorySize, SMEM2);

    prep_k<<<768, dim3(32, 8)>>>(mlp_w, self_w, neigh_w);
    gemm1_k<<<M_ROWS1 / 64, 256, SMEM1>>>(neigh, mlp_b);
    gemm2_k<<<B_SZ / 64, 256, SMEM2>>>(self_vecs, out);
}

// round 15
// speedup vs baseline: 1.1086x; 1.0002x over previous
#include <cuda_runtime.h>
#include <cuda_fp16.h>
#include <stdint.h>

#define DI __device__ __forceinline__

static constexpr int B_SZ = 8192, NNB = 32, DIN = 512, DHID = 512, DOUT = 512;
static constexpr int M_ROWS1 = B_SZ * NNB;     // 262144

// ---------------- device scratch ----------------
__device__ __half g_Wt1 [DHID * DIN];            // [n][k] = mlp_w[k][n]   (K-major)
__device__ __half g_Wcat[DOUT * (DIN + DHID)];   // [n][k] = k<512 ? self_w[k][n] : neigh_w[k-512][n]
__device__ __half g_pooled[B_SZ * DHID];         // fp16 max-pooled hidden

// ---------------- PTX helpers (sm_103 baseline; no tcgen05) ----------------
DI uint32_t su32(const void* p) {
    uint32_t a;
    asm("{ .reg .u64 t; cvta.to.shared.u64 t, %1; cvt.u32.u64 %0, t; }" : "=r"(a) : "l"(p));
    return a;
}
DI void cp16(uint32_t s, const void* g) {
    asm volatile("cp.async.cg.shared.global [%0], [%1], 16;" :: "r"(s), "l"(g));
}
DI void cp_commit() { asm volatile("cp.async.commit_group;"); }
template<int N> DI void cp_wait() { asm volatile("cp.async.wait_group %0;" :: "n"(N)); }

DI void ldm4(uint32_t* r, uint32_t a) {
    asm volatile("ldmatrix.sync.aligned.m8n8.x4.shared.b16 {%0,%1,%2,%3}, [%4];"
                 : "=r"(r[0]), "=r"(r[1]), "=r"(r[2]), "=r"(r[3]) : "r"(a));
}
DI void mma16816(float* c, const uint32_t* a, const uint32_t* b) {
    asm volatile(
        "mma.sync.aligned.m16n8k16.row.col.f32.f16.f16.f32 "
        "{%0,%1,%2,%3}, {%4,%5,%6,%7}, {%8,%9}, {%0,%1,%2,%3};"
        : "+f"(c[0]), "+f"(c[1]), "+f"(c[2]), "+f"(c[3])
        : "r"(a[0]), "r"(a[1]), "r"(a[2]), "r"(a[3]), "r"(b[0]), "r"(b[1]));
}
DI uint32_t h2u(__half2 h) { return *reinterpret_cast<uint32_t*>(&h); }

// ---------------- fused prepass (R11/R14-proven, verbatim) ----------------
__global__ void prep_k(const float* __restrict__ mlp_w,
                       const float* __restrict__ self_w,
                       const float* __restrict__ neigh_w) {
    const int job  = blockIdx.x >> 8;
    const int tile = blockIdx.x & 255;
    const float* __restrict__ src = (job == 0) ? mlp_w : (job == 1) ? self_w : neigh_w;
    __half* __restrict__ dst = (job == 0) ? g_Wt1 : g_Wcat;
    const int dstride = (job == 0) ? DIN : (DIN + DHID);
    const int koff    = (job == 2) ? DIN : 0;

    __shared__ float t[32][33];
    const int tx = threadIdx.x, ty = threadIdx.y;
    const int n0 = (tile & 15) * 32, k0 = (tile >> 4) * 32;
    #pragma unroll
    for (int j = 0; j < 4; ++j)
        t[ty + j * 8][tx] = src[(size_t)(k0 + ty + j * 8) * 512 + n0 + tx];
    __syncthreads();
    #pragma unroll
    for (int j = 0; j < 4; ++j) {
        int n = n0 + ty + j * 8, k = k0 + tx;
        dst[(size_t)n * dstride + koff + k] = __float2half(t[tx][ty + j * 8]);
    }
}

// ==================== STAGE 1 (R14 config + intra-k-tile register pipelining) ====================
// C[64,512] = fp16(neigh[m0..+63,:]) @ Wt1; bias+relu+max over the two 32-row
// neighbor groups -> g_pooled.  grid = 4096, 96 KB smem -> 2 CTAs/SM.
// Fragments double-buffered in registers: loads for ks+1 issue BEFORE the MMAs
// of ks, hiding LDSM latency behind the MMA stream. Barriers/buffers unchanged.
__global__ void __launch_bounds__(256, 2) gemm1_k(const float* __restrict__ Af,
                                                  const float* __restrict__ bias) {
    constexpr int KTOT = 512, NKT = 8, AROW = KTOT * 2;
    constexpr uint32_t ABYTES = 64 * AROW;                  // 64 KB
    constexpr uint32_t BS0 = ABYTES, BS1 = ABYTES + 16384;

    extern __shared__ char sm[];
    const uint32_t sb = su32(sm);
    const int tid = threadIdx.x;
    const int w = tid >> 5, lane = tid & 31;
    const int wm = w >> 2, wn = w & 3;            // 2 x 4 warps, warp tile 32x32
    const int lr = lane & 7, lg = lane >> 3;
    const int m0 = blockIdx.x * 64;

    auto As = [&](int m, int k8) -> uint32_t {
        return sb + (uint32_t)(m * AROW + ((k8 ^ (m & 7)) << 4));
    };
    auto Bs = [&](int buf, int n, int k8) -> uint32_t {
        return sb + (buf ? BS1 : BS0) + (uint32_t)(n * 128 + ((k8 ^ (n & 7)) << 4));
    };
    auto issueB = [&](int nb, int kt) {
        int buf = kt & 1;
        #pragma unroll
        for (int i = 0; i < 4; ++i) {             // 128 n x 8 chunks
            int ch = tid + i * 256;
            int n = ch >> 3, k8 = ch & 7;
            cp16(Bs(buf, n, k8), g_Wt1 + (size_t)(nb * 128 + n) * KTOT + kt * 64 + k8 * 8);
        }
        cp_commit();
    };

    issueB(0, 0);    // overlap first weight fetch with the A-load below

    // ---- A tile: 64 rows x 512 fp32 -> fp16 smem ----
    #pragma unroll
    for (int c = 0; c < 16; ++c) {                // 64 rows x 64 chunks
        int ch = tid + c * 256;
        int m = ch >> 6, k8 = ch & 63;
        const float* gp = Af + (size_t)(m0 + m) * 512 + k8 * 8;
        float4 f0 = *reinterpret_cast<const float4*>(gp);
        float4 f1 = *reinterpret_cast<const float4*>(gp + 4);
        uint4 u;
        u.x = h2u(__floats2half2_rn(f0.x, f0.y));
        u.y = h2u(__floats2half2_rn(f0.z, f0.w));
        u.z = h2u(__floats2half2_rn(f1.x, f1.y));
        u.w = h2u(__floats2half2_rn(f1.z, f1.w));
        *reinterpret_cast<uint4*>((char*)sm + (As(m, k8) - sb)) = u;
    }
    __syncthreads();

    // fragment row/col bases (constant per thread)
    const int am0 = wm * 32 + (lg & 1) * 8 + lr;          // + mi*16
    const int bn0 = wn * 32 + (lg >> 1) * 8 + lr;         // + nj*16
    const int aks = (lg >> 1);                            // k8 sub-offset for A
    const int bks = (lg & 1);                             // k8 sub-offset for B

    for (int nb = 0; nb < 4; ++nb) {
        float acc[2][4][4];
        #pragma unroll
        for (int mi = 0; mi < 2; ++mi)
            #pragma unroll
            for (int ni = 0; ni < 4; ++ni)
                #pragma unroll
                for (int q = 0; q < 4; ++q) acc[mi][ni][q] = 0.f;

        if (nb > 0) issueB(nb, 0);
        for (int kt = 0; kt < NKT; ++kt) {
            if (kt + 1 < NKT) { issueB(nb, kt + 1); cp_wait<1>(); }
            else             { cp_wait<0>(); }
            __syncthreads();

            const int buf = kt & 1;
            uint32_t afr[2][2][4], bfr[2][2][4];  // [pipe slot][mi/nj pair]

            // preload ks = 0 into slot 0
            ldm4(afr[0][0], As(am0,      kt * 8 + aks));
            ldm4(afr[0][1], As(am0 + 16, kt * 8 + aks));
            ldm4(bfr[0][0], Bs(buf, bn0,      bks));
            ldm4(bfr[0][1], Bs(buf, bn0 + 16, bks));

            #pragma unroll
            for (int ks = 0; ks < 4; ++ks) {
                const int cur = ks & 1, nxt = cur ^ 1;
                if (ks < 3) {                     // loads for ks+1 BEFORE MMAs of ks
                    const int k8g = kt * 8 + (ks + 1) * 2;
                    ldm4(afr[nxt][0], As(am0,      k8g + aks));
                    ldm4(afr[nxt][1], As(am0 + 16, k8g + aks));
                    ldm4(bfr[nxt][0], Bs(buf, bn0,      (ks + 1) * 2 + bks));
                    ldm4(bfr[nxt][1], Bs(buf, bn0 + 16, (ks + 1) * 2 + bks));
                }
                #pragma unroll
                for (int mi = 0; mi < 2; ++mi)
                    #pragma unroll
                    for (int ni = 0; ni < 4; ++ni)
                        mma16816(acc[mi][ni], afr[cur][mi], &bfr[cur][ni >> 1][(ni & 1) * 2]);
            }
            __syncthreads();
        }

        // ---- epilogue: warp wm's 32 rows = neighbors of batch blockIdx*2+wm ----
        const int n0w = nb * 128 + wn * 32;
        float v0[4], v1[4];
        #pragma unroll
        for (int ni = 0; ni < 4; ++ni) {
            v0[ni] = fmaxf(fmaxf(acc[0][ni][0], acc[0][ni][2]),
                           fmaxf(acc[1][ni][0], acc[1][ni][2]));
            v1[ni] = fmaxf(fmaxf(acc[0][ni][1], acc[0][ni][3]),
                           fmaxf(acc[1][ni][1], acc[1][ni][3]));
        }
        #pragma unroll
        for (int off = 4; off < 32; off <<= 1)
            #pragma unroll
            for (int ni = 0; ni < 4; ++ni) {
                v0[ni] = fmaxf(v0[ni], __shfl_xor_sync(0xffffffffu, v0[ni], off));
                v1[ni] = fmaxf(v1[ni], __shfl_xor_sync(0xffffffffu, v1[ni], off));
            }
        if (lane < 4) {
            size_t batch = (size_t)blockIdx.x * 2 + wm;
            #pragma unroll
            for (int ni = 0; ni < 4; ++ni) {
                int col = n0w + ni * 8 + lane * 2;
                float a0 = fmaxf(v0[ni] + __ldg(bias + col),     0.f);
                float a1 = fmaxf(v1[ni] + __ldg(bias + col + 1), 0.f);
                *reinterpret_cast<__half2*>(g_pooled + batch * DHID + col) =
                    __floats2half2_rn(a0, a1);
            }
        }
        __syncthreads();   // before next nb overwrites B buffers
    }
}

// ==================== STAGE 2 (R14-proven, verbatim) ====================
__global__ void __launch_bounds__(256, 1) gemm2_k(const float* __restrict__ selfv,
                                                  float* __restrict__ out) {
    constexpr int KTOT = 1024, NKT = 16, AROW = KTOT * 2;
    constexpr uint32_t ABYTES = 64 * AROW;                  // 128 KB
    constexpr uint32_t BS0 = ABYTES, BS1 = ABYTES + 16384;

    extern __shared__ char sm[];
    const uint32_t sb = su32(sm);
    const int tid = threadIdx.x;
    const int w = tid >> 5, lane = tid & 31;
    const int wm = w >> 2, wn = w & 3;
    const int lr = lane & 7, lg = lane >> 3;
    const int m0 = blockIdx.x * 64;

    auto As = [&](int m, int k8) -> uint32_t {
        return sb + (uint32_t)(m * AROW + ((k8 ^ (m & 7)) << 4));
    };
    auto Bs = [&](int buf, int n, int k8) -> uint32_t {
        return sb + (buf ? BS1 : BS0) + (uint32_t)(n * 128 + ((k8 ^ (n & 7)) << 4));
    };
    auto issueB = [&](int nb, int kt) {
        int buf = kt & 1;
        #pragma unroll
        for (int i = 0; i < 4; ++i) {
            int ch = tid + i * 256;
            int n = ch >> 3, k8 = ch & 7;
            cp16(Bs(buf, n, k8), g_Wcat + (size_t)(nb * 128 + n) * KTOT + kt * 64 + k8 * 8);
        }
        cp_commit();
    };

    issueB(0, 0);

    // ---- A tile, k[0:512): fp32 self_vecs converted inline ----
    #pragma unroll
    for (int c = 0; c < 16; ++c) {                // 64 rows x 64 chunks
        int ch = tid + c * 256;
        int m = ch >> 6, k8 = ch & 63;
        const float* gp = selfv + (size_t)(m0 + m) * 512 + k8 * 8;
        float4 f0 = *reinterpret_cast<const float4*>(gp);
        float4 f1 = *reinterpret_cast<const float4*>(gp + 4);
        uint4 u;
        u.x = h2u(__floats2half2_rn(f0.x, f0.y));
        u.y = h2u(__floats2half2_rn(f0.z, f0.w));
        u.z = h2u(__floats2half2_rn(f1.x, f1.y));
        u.w = h2u(__floats2half2_rn(f1.z, f1.w));
        *reinterpret_cast<uint4*>((char*)sm + (As(m, k8) - sb)) = u;
    }
    // ---- A tile, k[512:1024): fp16 pooled copy ----
    #pragma unroll
    for (int c = 0; c < 16; ++c) {                // 64 rows x 64 chunks
        int ch = tid + c * 256;
        int m = ch >> 6, k8 = ch & 63;
        *reinterpret_cast<uint4*>((char*)sm + (As(m, 64 + k8) - sb)) =
            *reinterpret_cast<const uint4*>(g_pooled + (size_t)(m0 + m) * DHID + k8 * 8);
    }
    __syncthreads();

    for (int nb = 0; nb < 4; ++nb) {
        float acc[2][4][4];
        #pragma unroll
        for (int mi = 0; mi < 2; ++mi)
            #pragma unroll
            for (int ni = 0; ni < 4; ++ni)
                #pragma unroll
                for (int q = 0; q < 4; ++q) acc[mi][ni][q] = 0.f;

        if (nb > 0) issueB(nb, 0);
        for (int kt = 0; kt < NKT; ++kt) {
            if (kt + 1 < NKT) { issueB(nb, kt + 1); cp_wait<1>(); }
            else             { cp_wait<0>(); }
            __syncthreads();

            const int buf = kt & 1;
            #pragma unroll
            for (int ks = 0; ks < 4; ++ks) {
                const int k8g = kt * 8 + ks * 2;
                uint32_t afr[2][4];
                #pragma unroll
                for (int mi = 0; mi < 2; ++mi) {
                    int m = wm * 32 + mi * 16 + (lg & 1) * 8 + lr;
                    ldm4(afr[mi], As(m, k8g + (lg >> 1)));
                }
                uint32_t bfr[2][4];
                #pragma unroll
                for (int nj = 0; nj < 2; ++nj) {
                    int n = wn * 32 + nj * 16 + (lg >> 1) * 8 + lr;
                    ldm4(bfr[nj], Bs(buf, n, ks * 2 + (lg & 1)));
                }
                #pragma unroll
                for (int mi = 0; mi < 2; ++mi)
                    #pragma unroll
                    for (int ni = 0; ni < 4; ++ni)
                        mma16816(acc[mi][ni], afr[mi], &bfr[ni >> 1][(ni & 1) * 2]);
            }
            __syncthreads();
        }

        const int n0w = nb * 128 + wn * 32;
        #pragma unroll
        for (int mi = 0; mi < 2; ++mi)
            #pragma unroll
            for (int h = 0; h < 2; ++h) {
                int m = m0 + wm * 32 + mi * 16 + (lane >> 2) + h * 8;
                #pragma unroll
                for (int ni = 0; ni < 4; ++ni) {
                    int col = n0w + ni * 8 + (lane & 3) * 2;
                    float2 v = make_float2(fmaxf(acc[mi][ni][h * 2],     0.f),
                                           fmaxf(acc[mi][ni][h * 2 + 1], 0.f));
                    *reinterpret_cast<float2*>(out + (size_t)m * DOUT + col) = v;
                }
            }
        __syncthreads();
    }
}

// ---------------- launch: 3 kernels total ----------------
extern "C" void kernel_launch(void* const* d_in, const int* in_sizes, int n_in,
                              void* d_out, int out_size) {
    const float* self_vecs = (const float*)d_in[0];
    const float* neigh     = (const float*)d_in[1];
    const float* mlp_w     = (const float*)d_in[2];
    const float* mlp_b     = (const float*)d_in[3];
    const float* neigh_w   = (const float*)d_in[4];
    const float* self_w    = (const float*)d_in[5];
    float* out = (float*)d_out;

    constexpr uint32_t SMEM1 = 64 * 1024 + 2 * 16384;    //  96 KB -> 2 CTAs/SM
    constexpr uint32_t SMEM2 = 128 * 1024 + 2 * 16384;   // 160 KB -> 1 CTA/SM
    cudaFuncSetAttribute(gemm1_k, cudaFuncAttributeMaxDynamicSharedMemorySize, SMEM1);
    cudaFuncSetAttribute(gemm2_k, cudaFuncAttributeMaxDynamicSharedMemorySize, SMEM2);

    prep_k<<<768, dim3(32, 8)>>>(mlp_w, self_w, neigh_w);
    gemm1_k<<<M_ROWS1 / 64, 256, SMEM1>>>(neigh, mlp_b);
    gemm2_k<<<B_SZ / 64, 256, SMEM2>>>(self_vecs, out);
}